// round 9
// baseline (speedup 1.0000x reference)
#include <cuda_runtime.h>
#include <cuda_bf16.h>
#include <math.h>

#define NN 50000
#define EE 1600000
#define IND 256
#define OUTD 64
#define NH 4
typedef unsigned long long ull;

// ---------------- scratch (static device arrays; zero-initialized) ----------
__device__ float  g_x[NN * OUTD];          // 12.8 MB  x = h@W
__device__ float4 g_el[NN];
__device__ float4 g_er[NN];
__device__ int    g_deg[NN];               // invariant: zero at kernel_launch entry
__device__ int    g_off[NN + 1];
__device__ int    g_cur[NN];
__device__ int    g_dst_s[EE];             // CSR-sorted dst

// ---------------- helpers ----------------------------------------------------
#define L2E 1.4426950408889634f

__device__ __forceinline__ float lrelu_exp(float v)
{
    return exp2f(fmaxf(v, 0.2f * v) * L2E);
}
__device__ __forceinline__ float elu1(float v)
{
    return (v > 0.f) ? v : expm1f(v);
}
union U64 { ull u; float2 f; };

// ---------------- K1: x = h @ W  (64-row tile, duplicated-B smem) ------------
// 64x64 tile, 256 threads, 4x4 microtile, f32x2 accumulation.
__global__ void __launch_bounds__(256) k_gemm(const float* __restrict__ h,
                                              const float* __restrict__ W, int N)
{
    __shared__ float As2[32][68];      // k-major, 64 rows, pad 68
    __shared__ float Bs2[32][132];     // k-major, 64 cols duplicated (128), pad 132

    const int tid = threadIdx.x;
    const int m0  = blockIdx.x * 64;
    const int tx  = tid & 15;          // col group (4 cols)
    const int ty  = tid >> 4;          // row group (4 rows)

    const int rowA = tid >> 3;         // 0..31
    const int kqA  = tid & 7;
    const int kkB  = tid >> 4;         // 0..15 (+16)
    const int nqB  = tid & 15;

    ull acc2[2][4];
#pragma unroll
    for (int r = 0; r < 2; r++)
#pragma unroll
        for (int j = 0; j < 4; j++) acc2[r][j] = 0ull;

    for (int k0 = 0; k0 < IND; k0 += 32) {
        // A tile: 64 rows x 32 k
#pragma unroll
        for (int l = 0; l < 2; l++) {
            int row = rowA + 32 * l;
            int gm  = m0 + row;
            float4 v = make_float4(0.f, 0.f, 0.f, 0.f);
            if (gm < N) v = *(const float4*)(h + (size_t)gm * IND + k0 + kqA * 4);
            As2[kqA * 4 + 0][row] = v.x;
            As2[kqA * 4 + 1][row] = v.y;
            As2[kqA * 4 + 2][row] = v.z;
            As2[kqA * 4 + 3][row] = v.w;
        }
        // B tile: duplicated pairs (x,x,y,y)(z,z,w,w)
#pragma unroll
        for (int l = 0; l < 2; l++) {
            int kk = kkB + 16 * l;
            float4 v = *(const float4*)(W + (size_t)(k0 + kk) * OUTD + nqB * 4);
            *(float4*)&Bs2[kk][nqB * 8]     = make_float4(v.x, v.x, v.y, v.y);
            *(float4*)&Bs2[kk][nqB * 8 + 4] = make_float4(v.z, v.z, v.w, v.w);
        }
        __syncthreads();

#pragma unroll
        for (int k = 0; k < 32; k++) {
            float4 af = *(const float4*)&As2[k][ty * 4];      // rows ty*4..+3
            U64 a0, a1; a0.f = make_float2(af.x, af.y); a1.f = make_float2(af.z, af.w);
            const ull* bp = (const ull*)&Bs2[k][tx * 8];
            ull b0 = bp[0], b1 = bp[1], b2 = bp[2], b3 = bp[3];
            asm("fma.rn.f32x2 %0, %1, %2, %0;" : "+l"(acc2[0][0]) : "l"(b0), "l"(a0.u));
            asm("fma.rn.f32x2 %0, %1, %2, %0;" : "+l"(acc2[0][1]) : "l"(b1), "l"(a0.u));
            asm("fma.rn.f32x2 %0, %1, %2, %0;" : "+l"(acc2[0][2]) : "l"(b2), "l"(a0.u));
            asm("fma.rn.f32x2 %0, %1, %2, %0;" : "+l"(acc2[0][3]) : "l"(b3), "l"(a0.u));
            asm("fma.rn.f32x2 %0, %1, %2, %0;" : "+l"(acc2[1][0]) : "l"(b0), "l"(a1.u));
            asm("fma.rn.f32x2 %0, %1, %2, %0;" : "+l"(acc2[1][1]) : "l"(b1), "l"(a1.u));
            asm("fma.rn.f32x2 %0, %1, %2, %0;" : "+l"(acc2[1][2]) : "l"(b2), "l"(a1.u));
            asm("fma.rn.f32x2 %0, %1, %2, %0;" : "+l"(acc2[1][3]) : "l"(b3), "l"(a1.u));
        }
        __syncthreads();
    }

    // acc2[r][j] holds (row pair lanes) x-dup? NO: here a holds A row-pairs?
    // Note: packing is (A rows ty*4+{0,1}) in a0 lanes, b duplicated per col j ->
    // acc2[0][j] = ( row ty*4+0 col j*? , row ty*4+1 col j*? ) per-lane:
    //   lane0: A(row ty*4+0)*B(col 2j? ) -- careful: b0 = (W[c0],W[c0]) dup,
    //   so acc2[0][j].x = sum A(row0,k)*W(k,c_j) with c_j = tx*4+j. Correct:
    //   acc2[r][j] packs rows (ty*4+2r, ty*4+2r+1) for col tx*4+j.
#pragma unroll
    for (int r = 0; r < 2; r++) {
        int gm0 = m0 + ty * 4 + 2 * r;
        U64 t0, t1, t2, t3;
        t0.u = acc2[r][0]; t1.u = acc2[r][1]; t2.u = acc2[r][2]; t3.u = acc2[r][3];
        if (gm0 < N)
            *(float4*)(g_x + (size_t)gm0 * OUTD + tx * 4) =
                make_float4(t0.f.x, t1.f.x, t2.f.x, t3.f.x);
        if (gm0 + 1 < N)
            *(float4*)(g_x + (size_t)(gm0 + 1) * OUTD + tx * 4) =
                make_float4(t0.f.y, t1.f.y, t2.f.y, t3.f.y);
    }
}

// ---------------- K2: degree histogram ---------------------------------------
__global__ void k_deg(const int* __restrict__ ei, int E)
{
    int stride = gridDim.x * blockDim.x;
    const int4* e4 = (const int4*)ei;
    int E4 = E >> 2;
    for (int i = blockIdx.x * blockDim.x + threadIdx.x; i < E4; i += stride) {
        int4 v = e4[i];
        atomicAdd(&g_deg[v.x], 1);
        atomicAdd(&g_deg[v.y], 1);
        atomicAdd(&g_deg[v.z], 1);
        atomicAdd(&g_deg[v.w], 1);
    }
    for (int e = (E & ~3) + blockIdx.x * blockDim.x + threadIdx.x; e < E; e += stride)
        atomicAdd(&g_deg[ei[e]], 1);
}

// ---------------- K3: exclusive scan + deg re-zero ---------------------------
__global__ void k_scan(int N)
{
    __shared__ int sm[1024];
    const int t  = threadIdx.x;
    const int CH = (N + 1023) / 1024;
    int beg = t * CH;
    int end = beg + CH; if (end > N) end = N;

    int s = 0;
    for (int i = beg; i < end; i++) s += g_deg[i];
    sm[t] = s;
    __syncthreads();
#pragma unroll
    for (int o = 1; o < 1024; o <<= 1) {
        int v = (t >= o) ? sm[t - o] : 0;
        __syncthreads();
        sm[t] += v;
        __syncthreads();
    }
    int run = sm[t] - s;
    for (int i = beg; i < end; i++) {
        int dv = g_deg[i];
        g_off[i] = run;
        g_cur[i] = run;
        g_deg[i] = 0;
        run += dv;
    }
    if (t == 1023) g_off[N] = sm[1023];
}

// ---------------- K4: CSR scatter (dst only), 4 edges/thread -----------------
__global__ void k_scatter(const int* __restrict__ ei, int E)
{
    int i = blockIdx.x * blockDim.x + threadIdx.x;
    int e = i * 4;
    if (((E & 3) == 0) && (e + 4 <= E)) {
        int4 s4 = *(const int4*)(ei + e);
        int4 d4 = *(const int4*)(ei + E + e);
        g_dst_s[atomicAdd(&g_cur[s4.x], 1)] = d4.x;
        g_dst_s[atomicAdd(&g_cur[s4.y], 1)] = d4.y;
        g_dst_s[atomicAdd(&g_cur[s4.z], 1)] = d4.z;
        g_dst_s[atomicAdd(&g_cur[s4.w], 1)] = d4.w;
    } else {
        for (int q = e; q < E && q < e + 4; q++) {
            int s = ei[q];
            int d = ei[E + q];
            g_dst_s[atomicAdd(&g_cur[s], 1)] = d;
        }
    }
}

// ---------------- K5: el/er projections (warp per node) ----------------------
__global__ void k_elr(const float* __restrict__ Wl, const float* __restrict__ Wr, int N)
{
    int warp = (blockIdx.x * blockDim.x + threadIdx.x) >> 5;
    int lane = threadIdx.x & 31;
    if (warp >= N) return;

    const float* xr = g_x + (size_t)warp * OUTD;
    float x0 = xr[lane];
    float x1 = xr[lane + 32];

    float s[8];
#pragma unroll
    for (int hd = 0; hd < NH; hd++) {
        s[hd]     = x0 * __ldg(Wl + hd * OUTD + lane) + x1 * __ldg(Wl + hd * OUTD + lane + 32);
        s[4 + hd] = x0 * __ldg(Wr + hd * OUTD + lane) + x1 * __ldg(Wr + hd * OUTD + lane + 32);
    }
#pragma unroll
    for (int o = 16; o > 0; o >>= 1) {
#pragma unroll
        for (int j = 0; j < 8; j++) s[j] += __shfl_xor_sync(0xffffffffu, s[j], o);
    }
    if (lane == 0) {
        g_el[warp] = make_float4(s[0], s[1], s[2], s[3]);
        g_er[warp] = make_float4(s[4], s[5], s[6], s[7]);
    }
}

// ---------------- K6: per-node aggregation (round-7 proven version) ----------
__global__ void __launch_bounds__(128) k_agg(const float* __restrict__ b,
                                             float* __restrict__ out, int N)
{
    __shared__ int    s_off[2][4][32];
    __shared__ float4 s_e[2][4][32][2];

    const int w    = threadIdx.x >> 5;
    const int lane = threadIdx.x & 31;
    const int node = blockIdx.x * 4 + w;
    if (node >= N) return;

    const int s0 = g_off[node];
    const int s1 = g_off[node + 1];
    const float4 el = g_el[node];

    ull a0 = 0ull, a1 = 0ull, a2 = 0ull, a3 = 0ull;
    float e0 = 0.f, e1 = 0.f, e2 = 0.f, e3 = 0.f;

    const float* xl = g_x + lane * 2;

    auto stage = [&](int buf, int c, int n) {
        if (lane < n) {
            int d = g_dst_s[c + lane];
            float4 er = g_er[d];
            float ex = lrelu_exp(el.x + er.x);
            float ey = lrelu_exp(el.y + er.y);
            float ez = lrelu_exp(el.z + er.z);
            float ew = lrelu_exp(el.w + er.w);
            e0 += ex; e1 += ey; e2 += ez; e3 += ew;
            s_off[buf][w][lane]  = d * OUTD;
            s_e[buf][w][lane][0] = make_float4(ex, ex, ey, ey);
            s_e[buf][w][lane][1] = make_float4(ez, ez, ew, ew);
        }
    };

    auto consume32 = [&](int buf) {
        int oo0[4], oo1[4]; ull xx0[4], xx1[4];
#pragma unroll
        for (int q = 0; q < 4; q++) oo0[q] = s_off[buf][w][q];
#pragma unroll
        for (int q = 0; q < 4; q++) xx0[q] = *(const ull*)(xl + oo0[q]);
#pragma unroll
        for (int g = 0; g < 8; g++) {
            if (g < 7) {
#pragma unroll
                for (int q = 0; q < 4; q++) oo1[q] = s_off[buf][w][(g + 1) * 4 + q];
#pragma unroll
                for (int q = 0; q < 4; q++) xx1[q] = *(const ull*)(xl + oo1[q]);
            }
            ulonglong2 pa[4], pb[4];
#pragma unroll
            for (int q = 0; q < 4; q++) {
                pa[q] = *(const ulonglong2*)&s_e[buf][w][g * 4 + q][0];
                pb[q] = *(const ulonglong2*)&s_e[buf][w][g * 4 + q][1];
            }
#pragma unroll
            for (int q = 0; q < 4; q++) {
                asm("fma.rn.f32x2 %0, %1, %2, %0;" : "+l"(a0) : "l"(pa[q].x), "l"(xx0[q]));
                asm("fma.rn.f32x2 %0, %1, %2, %0;" : "+l"(a1) : "l"(pa[q].y), "l"(xx0[q]));
                asm("fma.rn.f32x2 %0, %1, %2, %0;" : "+l"(a2) : "l"(pb[q].x), "l"(xx0[q]));
                asm("fma.rn.f32x2 %0, %1, %2, %0;" : "+l"(a3) : "l"(pb[q].y), "l"(xx0[q]));
            }
#pragma unroll
            for (int q = 0; q < 4; q++) { xx0[q] = xx1[q]; oo0[q] = oo1[q]; }
        }
    };

    auto consumeTail = [&](int buf, int n) {
        for (int j = 0; j < n; j++) {
            int off = s_off[buf][w][j];
            ulonglong2 p0 = *(const ulonglong2*)&s_e[buf][w][j][0];
            ulonglong2 p1 = *(const ulonglong2*)&s_e[buf][w][j][1];
            ull xv = *(const ull*)(xl + off);
            asm("fma.rn.f32x2 %0, %1, %2, %0;" : "+l"(a0) : "l"(p0.x), "l"(xv));
            asm("fma.rn.f32x2 %0, %1, %2, %0;" : "+l"(a1) : "l"(p0.y), "l"(xv));
            asm("fma.rn.f32x2 %0, %1, %2, %0;" : "+l"(a2) : "l"(p1.x), "l"(xv));
            asm("fma.rn.f32x2 %0, %1, %2, %0;" : "+l"(a3) : "l"(p1.y), "l"(xv));
        }
    };

    int c = s0;
    int buf = 0;
    int n0 = s1 - c; if (n0 > 32) n0 = 32;
    stage(0, c, n0);
    __syncwarp();

    while (c + 32 < s1) {
        int cn = c + 32;
        int nn = s1 - cn; if (nn > 32) nn = 32;
        stage(buf ^ 1, cn, nn);
        consume32(buf);
        __syncwarp();
        buf ^= 1;
        c = cn;
    }
    {
        int n = s1 - c;
        if (n == 32) consume32(buf);
        else if (n > 0) consumeTail(buf, n);
    }

#pragma unroll
    for (int o = 16; o > 0; o >>= 1) {
        e0 += __shfl_xor_sync(0xffffffffu, e0, o);
        e1 += __shfl_xor_sync(0xffffffffu, e1, o);
        e2 += __shfl_xor_sync(0xffffffffu, e2, o);
        e3 += __shfl_xor_sync(0xffffffffu, e3, o);
    }

    float i0 = 1.f / fmaxf(e0, 1e-12f);
    float i1 = 1.f / fmaxf(e1, 1e-12f);
    float i2 = 1.f / fmaxf(e2, 1e-12f);
    float i3 = 1.f / fmaxf(e3, 1e-12f);

    float2 bb = *(const float2*)(b + lane * 2);

    U64 A0, A1, A2, A3;
    A0.u = a0; A1.u = a1; A2.u = a2; A3.u = a3;

    float* o = out + (size_t)node * (NH * OUTD) + lane * 2;
    float2 r;
    r.x = elu1(A0.f.x * i0 + bb.x); r.y = elu1(A0.f.y * i0 + bb.y);
    *(float2*)(o + 0 * OUTD) = r;
    r.x = elu1(A1.f.x * i1 + bb.x); r.y = elu1(A1.f.y * i1 + bb.y);
    *(float2*)(o + 1 * OUTD) = r;
    r.x = elu1(A2.f.x * i2 + bb.x); r.y = elu1(A2.f.y * i2 + bb.y);
    *(float2*)(o + 2 * OUTD) = r;
    r.x = elu1(A3.f.x * i3 + bb.x); r.y = elu1(A3.f.y * i3 + bb.y);
    *(float2*)(o + 3 * OUTD) = r;
}

// ---------------- launch: fork-join two-stream graph --------------------------
extern "C" void kernel_launch(void* const* d_in, const int* in_sizes, int n_in,
                              void* d_out, int out_size)
{
    const float* h  = (const float*)d_in[0];   // [N, 256]
    const float* W  = (const float*)d_in[1];   // [256, 64]
    const float* Wl = (const float*)d_in[2];   // [4, 64]
    const float* Wr = (const float*)d_in[3];   // [4, 64]
    const float* b  = (const float*)d_in[4];   // [64]
    const int*   ei = (const int*)d_in[5];     // [2, E]
    float* out = (float*)d_out;

    int N = in_sizes[0] / IND;
    int E = in_sizes[5] / 2;

    static cudaStream_t s1 = nullptr;
    static cudaEvent_t  evFork = nullptr, evJoin = nullptr;
    if (s1 == nullptr) {
        cudaStreamCreateWithFlags(&s1, cudaStreamNonBlocking);
        cudaEventCreateWithFlags(&evFork, cudaEventDisableTiming);
        cudaEventCreateWithFlags(&evJoin, cudaEventDisableTiming);
    }

    // fork: s1 handles the CSR-build chain (independent of the GEMM)
    cudaEventRecord(evFork, 0);
    cudaStreamWaitEvent(s1, evFork, 0);

    k_deg<<<512, 256, 0, s1>>>(ei, E);
    k_scan<<<1, 1024, 0, s1>>>(N);
    int SB = ((E + 3) / 4 + 255) / 256;
    k_scatter<<<SB, 256, 0, s1>>>(ei, E);
    cudaEventRecord(evJoin, s1);

    // main stream: gemm -> elr
    k_gemm<<<(N + 63) / 64, 256>>>(h, W, N);
    k_elr<<<(N + 7) / 8, 256>>>(Wl, Wr, N);

    // join: agg needs CSR (s1) + el/er (main)
    cudaStreamWaitEvent(0, evJoin, 0);
    k_agg<<<(N + 3) / 4, 128>>>(b, out, N);
}

// round 10
// speedup vs baseline: 1.5793x; 1.5793x over previous
#include <cuda_runtime.h>
#include <cuda_bf16.h>
#include <math.h>
#include <stdint.h>

#define NN 50000
#define EE 1600000
#define IND 256
#define OUTD 64
#define NH 4
typedef unsigned long long ull;

// ---------------- scratch (static device arrays; zero-initialized) ----------
__device__ float  g_x[NN * OUTD];          // 12.8 MB  x = h@W
__device__ float4 g_el[NN];
__device__ float4 g_er[NN];
__device__ int    g_deg[NN];               // invariant: zero at kernel_launch entry
__device__ int    g_off[NN + 1];
__device__ int    g_cur[NN];
__device__ int    g_dst_s[EE];             // CSR-sorted dst

// ---------------- helpers ----------------------------------------------------
#define L2E 1.4426950408889634f

__device__ __forceinline__ float lrelu_exp(float v)
{
    return exp2f(fmaxf(v, 0.2f * v) * L2E);
}
__device__ __forceinline__ float elu1(float v)
{
    return (v > 0.f) ? v : expm1f(v);
}
__device__ __forceinline__ uint32_t f2tf32(float v)
{
    uint32_t r; asm("cvt.rna.tf32.f32 %0, %1;" : "=r"(r) : "f"(v)); return r;
}
union U64 { ull u; float2 f; };

// ---------------- K1: x = h @ W  (tf32 tensor-core mma) -----------------------
// 128x64 tile per block, 256 threads (8 warps), warp owns 16 rows x 64 cols.
__global__ void __launch_bounds__(256) k_gemm(const float* __restrict__ h,
                                              const float* __restrict__ W, int N)
{
    __shared__ uint32_t As[128][36];    // tf32 bits, row-major [m][k], pad 36
    __shared__ uint32_t Bs[32][72];     // tf32 bits, [k][n], pad 72

    const int tid  = threadIdx.x;
    const int m0   = blockIdx.x * 128;
    const int w    = tid >> 5;
    const int lane = tid & 31;
    const int lq   = lane >> 2;         // 0..7
    const int lr   = lane & 3;          // 0..3

    const int rowA = tid >> 3;          // 0..31 (+32*l)
    const int kqA  = tid & 7;
    const int kkB  = tid >> 4;          // 0..15 (+16)
    const int nqB  = tid & 15;

    float c[8][4];
#pragma unroll
    for (int nt = 0; nt < 8; nt++)
#pragma unroll
        for (int j = 0; j < 4; j++) c[nt][j] = 0.f;

    for (int k0 = 0; k0 < IND; k0 += 32) {
        // ---- A tile: 128 rows x 32 k, cvt to tf32, STS.128 ----
#pragma unroll
        for (int l = 0; l < 4; l++) {
            int row = rowA + 32 * l;
            int gm  = m0 + row;
            float4 v = make_float4(0.f, 0.f, 0.f, 0.f);
            if (gm < N) v = *(const float4*)(h + (size_t)gm * IND + k0 + kqA * 4);
            uint4 t;
            t.x = f2tf32(v.x); t.y = f2tf32(v.y); t.z = f2tf32(v.z); t.w = f2tf32(v.w);
            *(uint4*)&As[row][kqA * 4] = t;
        }
        // ---- B tile: 32 k x 64 n ----
#pragma unroll
        for (int l = 0; l < 2; l++) {
            int kk = kkB + 16 * l;
            float4 v = *(const float4*)(W + (size_t)(k0 + kk) * OUTD + nqB * 4);
            uint4 t;
            t.x = f2tf32(v.x); t.y = f2tf32(v.y); t.z = f2tf32(v.z); t.w = f2tf32(v.w);
            *(uint4*)&Bs[kk][nqB * 4] = t;
        }
        __syncthreads();

#pragma unroll
        for (int kk = 0; kk < 32; kk += 8) {
            // A fragment m16k8 (rows w*16 + lq, +8)
            uint32_t a0 = As[w * 16 + lq][kk + lr];
            uint32_t a1 = As[w * 16 + lq + 8][kk + lr];
            uint32_t a2 = As[w * 16 + lq][kk + lr + 4];
            uint32_t a3 = As[w * 16 + lq + 8][kk + lr + 4];
#pragma unroll
            for (int nt = 0; nt < 8; nt++) {
                uint32_t b0 = Bs[kk + lr][nt * 8 + lq];
                uint32_t b1 = Bs[kk + lr + 4][nt * 8 + lq];
                asm("mma.sync.aligned.m16n8k8.row.col.f32.tf32.tf32.f32 "
                    "{%0,%1,%2,%3}, {%4,%5,%6,%7}, {%8,%9}, {%0,%1,%2,%3};"
                    : "+f"(c[nt][0]), "+f"(c[nt][1]), "+f"(c[nt][2]), "+f"(c[nt][3])
                    : "r"(a0), "r"(a1), "r"(a2), "r"(a3), "r"(b0), "r"(b1));
            }
        }
        __syncthreads();
    }

    // epilogue: c[nt]: (row=lq(+8), col=nt*8 + lr*2 (+1))
    const int r0 = m0 + w * 16 + lq;
#pragma unroll
    for (int nt = 0; nt < 8; nt++) {
        if (r0 < N)
            *(float2*)(g_x + (size_t)r0 * OUTD + nt * 8 + lr * 2) =
                make_float2(c[nt][0], c[nt][1]);
        if (r0 + 8 < N)
            *(float2*)(g_x + (size_t)(r0 + 8) * OUTD + nt * 8 + lr * 2) =
                make_float2(c[nt][2], c[nt][3]);
    }
}

// ---------------- K2: degree histogram ---------------------------------------
__global__ void k_deg(const int* __restrict__ ei, int E)
{
    int stride = gridDim.x * blockDim.x;
    const int4* e4 = (const int4*)ei;
    int E4 = E >> 2;
    for (int i = blockIdx.x * blockDim.x + threadIdx.x; i < E4; i += stride) {
        int4 v = e4[i];
        atomicAdd(&g_deg[v.x], 1);
        atomicAdd(&g_deg[v.y], 1);
        atomicAdd(&g_deg[v.z], 1);
        atomicAdd(&g_deg[v.w], 1);
    }
    for (int e = (E & ~3) + blockIdx.x * blockDim.x + threadIdx.x; e < E; e += stride)
        atomicAdd(&g_deg[ei[e]], 1);
}

// ---------------- K3: exclusive scan + deg re-zero ---------------------------
__global__ void k_scan(int N)
{
    __shared__ int sm[1024];
    const int t  = threadIdx.x;
    const int CH = (N + 1023) / 1024;
    int beg = t * CH;
    int end = beg + CH; if (end > N) end = N;

    int s = 0;
    for (int i = beg; i < end; i++) s += g_deg[i];
    sm[t] = s;
    __syncthreads();
#pragma unroll
    for (int o = 1; o < 1024; o <<= 1) {
        int v = (t >= o) ? sm[t - o] : 0;
        __syncthreads();
        sm[t] += v;
        __syncthreads();
    }
    int run = sm[t] - s;
    for (int i = beg; i < end; i++) {
        int dv = g_deg[i];
        g_off[i] = run;
        g_cur[i] = run;
        g_deg[i] = 0;
        run += dv;
    }
    if (t == 1023) g_off[N] = sm[1023];
}

// ---------------- K4: CSR scatter (dst only), 4 edges/thread -----------------
__global__ void k_scatter(const int* __restrict__ ei, int E)
{
    int i = blockIdx.x * blockDim.x + threadIdx.x;
    int e = i * 4;
    if (((E & 3) == 0) && (e + 4 <= E)) {
        int4 s4 = *(const int4*)(ei + e);
        int4 d4 = *(const int4*)(ei + E + e);
        g_dst_s[atomicAdd(&g_cur[s4.x], 1)] = d4.x;
        g_dst_s[atomicAdd(&g_cur[s4.y], 1)] = d4.y;
        g_dst_s[atomicAdd(&g_cur[s4.z], 1)] = d4.z;
        g_dst_s[atomicAdd(&g_cur[s4.w], 1)] = d4.w;
    } else {
        for (int q = e; q < E && q < e + 4; q++) {
            int s = ei[q];
            int d = ei[E + q];
            g_dst_s[atomicAdd(&g_cur[s], 1)] = d;
        }
    }
}

// ---------------- K5: el/er projections (warp per node) ----------------------
__global__ void k_elr(const float* __restrict__ Wl, const float* __restrict__ Wr, int N)
{
    int warp = (blockIdx.x * blockDim.x + threadIdx.x) >> 5;
    int lane = threadIdx.x & 31;
    if (warp >= N) return;

    const float* xr = g_x + (size_t)warp * OUTD;
    float x0 = xr[lane];
    float x1 = xr[lane + 32];

    float s[8];
#pragma unroll
    for (int hd = 0; hd < NH; hd++) {
        s[hd]     = x0 * __ldg(Wl + hd * OUTD + lane) + x1 * __ldg(Wl + hd * OUTD + lane + 32);
        s[4 + hd] = x0 * __ldg(Wr + hd * OUTD + lane) + x1 * __ldg(Wr + hd * OUTD + lane + 32);
    }
#pragma unroll
    for (int o = 16; o > 0; o >>= 1) {
#pragma unroll
        for (int j = 0; j < 8; j++) s[j] += __shfl_xor_sync(0xffffffffu, s[j], o);
    }
    if (lane == 0) {
        g_el[warp] = make_float4(s[0], s[1], s[2], s[3]);
        g_er[warp] = make_float4(s[4], s[5], s[6], s[7]);
    }
}

// ---------------- K6: per-node aggregation (round-7 proven version) ----------
__global__ void __launch_bounds__(128) k_agg(const float* __restrict__ b,
                                             float* __restrict__ out, int N)
{
    __shared__ int    s_off[2][4][32];
    __shared__ float4 s_e[2][4][32][2];

    const int w    = threadIdx.x >> 5;
    const int lane = threadIdx.x & 31;
    const int node = blockIdx.x * 4 + w;
    if (node >= N) return;

    const int s0 = g_off[node];
    const int s1 = g_off[node + 1];
    const float4 el = g_el[node];

    ull a0 = 0ull, a1 = 0ull, a2 = 0ull, a3 = 0ull;
    float e0 = 0.f, e1 = 0.f, e2 = 0.f, e3 = 0.f;

    const float* xl = g_x + lane * 2;

    auto stage = [&](int buf, int c, int n) {
        if (lane < n) {
            int d = g_dst_s[c + lane];
            float4 er = g_er[d];
            float ex = lrelu_exp(el.x + er.x);
            float ey = lrelu_exp(el.y + er.y);
            float ez = lrelu_exp(el.z + er.z);
            float ew = lrelu_exp(el.w + er.w);
            e0 += ex; e1 += ey; e2 += ez; e3 += ew;
            s_off[buf][w][lane]  = d * OUTD;
            s_e[buf][w][lane][0] = make_float4(ex, ex, ey, ey);
            s_e[buf][w][lane][1] = make_float4(ez, ez, ew, ew);
        }
    };

    auto consume32 = [&](int buf) {
        int oo0[4], oo1[4]; ull xx0[4], xx1[4];
#pragma unroll
        for (int q = 0; q < 4; q++) oo0[q] = s_off[buf][w][q];
#pragma unroll
        for (int q = 0; q < 4; q++) xx0[q] = *(const ull*)(xl + oo0[q]);
#pragma unroll
        for (int g = 0; g < 8; g++) {
            if (g < 7) {
#pragma unroll
                for (int q = 0; q < 4; q++) oo1[q] = s_off[buf][w][(g + 1) * 4 + q];
#pragma unroll
                for (int q = 0; q < 4; q++) xx1[q] = *(const ull*)(xl + oo1[q]);
            }
            ulonglong2 pa[4], pb[4];
#pragma unroll
            for (int q = 0; q < 4; q++) {
                pa[q] = *(const ulonglong2*)&s_e[buf][w][g * 4 + q][0];
                pb[q] = *(const ulonglong2*)&s_e[buf][w][g * 4 + q][1];
            }
#pragma unroll
            for (int q = 0; q < 4; q++) {
                asm("fma.rn.f32x2 %0, %1, %2, %0;" : "+l"(a0) : "l"(pa[q].x), "l"(xx0[q]));
                asm("fma.rn.f32x2 %0, %1, %2, %0;" : "+l"(a1) : "l"(pa[q].y), "l"(xx0[q]));
                asm("fma.rn.f32x2 %0, %1, %2, %0;" : "+l"(a2) : "l"(pb[q].x), "l"(xx0[q]));
                asm("fma.rn.f32x2 %0, %1, %2, %0;" : "+l"(a3) : "l"(pb[q].y), "l"(xx0[q]));
            }
#pragma unroll
            for (int q = 0; q < 4; q++) { xx0[q] = xx1[q]; oo0[q] = oo1[q]; }
        }
    };

    auto consumeTail = [&](int buf, int n) {
        for (int j = 0; j < n; j++) {
            int off = s_off[buf][w][j];
            ulonglong2 p0 = *(const ulonglong2*)&s_e[buf][w][j][0];
            ulonglong2 p1 = *(const ulonglong2*)&s_e[buf][w][j][1];
            ull xv = *(const ull*)(xl + off);
            asm("fma.rn.f32x2 %0, %1, %2, %0;" : "+l"(a0) : "l"(p0.x), "l"(xv));
            asm("fma.rn.f32x2 %0, %1, %2, %0;" : "+l"(a1) : "l"(p0.y), "l"(xv));
            asm("fma.rn.f32x2 %0, %1, %2, %0;" : "+l"(a2) : "l"(p1.x), "l"(xv));
            asm("fma.rn.f32x2 %0, %1, %2, %0;" : "+l"(a3) : "l"(p1.y), "l"(xv));
        }
    };

    int c = s0;
    int buf = 0;
    int n0 = s1 - c; if (n0 > 32) n0 = 32;
    stage(0, c, n0);
    __syncwarp();

    while (c + 32 < s1) {
        int cn = c + 32;
        int nn = s1 - cn; if (nn > 32) nn = 32;
        stage(buf ^ 1, cn, nn);
        consume32(buf);
        __syncwarp();
        buf ^= 1;
        c = cn;
    }
    {
        int n = s1 - c;
        if (n == 32) consume32(buf);
        else if (n > 0) consumeTail(buf, n);
    }

#pragma unroll
    for (int o = 16; o > 0; o >>= 1) {
        e0 += __shfl_xor_sync(0xffffffffu, e0, o);
        e1 += __shfl_xor_sync(0xffffffffu, e1, o);
        e2 += __shfl_xor_sync(0xffffffffu, e2, o);
        e3 += __shfl_xor_sync(0xffffffffu, e3, o);
    }

    float i0 = 1.f / fmaxf(e0, 1e-12f);
    float i1 = 1.f / fmaxf(e1, 1e-12f);
    float i2 = 1.f / fmaxf(e2, 1e-12f);
    float i3 = 1.f / fmaxf(e3, 1e-12f);

    float2 bb = *(const float2*)(b + lane * 2);

    U64 A0, A1, A2, A3;
    A0.u = a0; A1.u = a1; A2.u = a2; A3.u = a3;

    float* o = out + (size_t)node * (NH * OUTD) + lane * 2;
    float2 r;
    r.x = elu1(A0.f.x * i0 + bb.x); r.y = elu1(A0.f.y * i0 + bb.y);
    *(float2*)(o + 0 * OUTD) = r;
    r.x = elu1(A1.f.x * i1 + bb.x); r.y = elu1(A1.f.y * i1 + bb.y);
    *(float2*)(o + 1 * OUTD) = r;
    r.x = elu1(A2.f.x * i2 + bb.x); r.y = elu1(A2.f.y * i2 + bb.y);
    *(float2*)(o + 2 * OUTD) = r;
    r.x = elu1(A3.f.x * i3 + bb.x); r.y = elu1(A3.f.y * i3 + bb.y);
    *(float2*)(o + 3 * OUTD) = r;
}

// ---------------- launch: fork-join two-stream graph --------------------------
extern "C" void kernel_launch(void* const* d_in, const int* in_sizes, int n_in,
                              void* d_out, int out_size)
{
    const float* h  = (const float*)d_in[0];   // [N, 256]
    const float* W  = (const float*)d_in[1];   // [256, 64]
    const float* Wl = (const float*)d_in[2];   // [4, 64]
    const float* Wr = (const float*)d_in[3];   // [4, 64]
    const float* b  = (const float*)d_in[4];   // [64]
    const int*   ei = (const int*)d_in[5];     // [2, E]
    float* out = (float*)d_out;

    int N = in_sizes[0] / IND;
    int E = in_sizes[5] / 2;

    static cudaStream_t s1 = nullptr;
    static cudaEvent_t  evFork = nullptr, evJoin = nullptr;
    if (s1 == nullptr) {
        cudaStreamCreateWithFlags(&s1, cudaStreamNonBlocking);
        cudaEventCreateWithFlags(&evFork, cudaEventDisableTiming);
        cudaEventCreateWithFlags(&evJoin, cudaEventDisableTiming);
    }

    // fork: s1 handles the CSR-build chain (independent of the GEMM)
    cudaEventRecord(evFork, 0);
    cudaStreamWaitEvent(s1, evFork, 0);

    k_deg<<<512, 256, 0, s1>>>(ei, E);
    k_scan<<<1, 1024, 0, s1>>>(N);
    int SB = ((E + 3) / 4 + 255) / 256;
    k_scatter<<<SB, 256, 0, s1>>>(ei, E);
    cudaEventRecord(evJoin, s1);

    // main stream: gemm -> elr
    k_gemm<<<(N + 127) / 128, 256>>>(h, W, N);
    k_elr<<<(N + 7) / 8, 256>>>(Wl, Wr, N);

    // join: agg needs CSR (s1) + el/er (main)
    cudaStreamWaitEvent(0, evJoin, 0);
    k_agg<<<(N + 3) / 4, 128>>>(b, out, N);
}

// round 11
// speedup vs baseline: 2.0582x; 1.3033x over previous
#include <cuda_runtime.h>
#include <cuda_bf16.h>
#include <math.h>
#include <stdint.h>

#define NN 50000
#define EE 1600000
#define IND 256
#define OUTD 64
#define NH 4
#define CSRB 512                    // blocks in the persistent CSR kernel
typedef unsigned long long ull;

// ---------------- scratch (static device arrays; zero-initialized) ----------
__device__ float  g_x[NN * OUTD];          // 12.8 MB  x = h@W
__device__ float4 g_el[NN];
__device__ float4 g_er[NN];
__device__ int    g_deg[NN];               // invariant: zero at kernel_launch entry
__device__ int    g_off[NN + 1];
__device__ int    g_cur[NN];
__device__ int    g_dst_s[EE];             // CSR-sorted dst
__device__ int    g_blk[CSRB];
__device__ int    g_blkoff[CSRB];
__device__ unsigned g_cnt;                 // grid-barrier arrivals (monotonic)
__device__ unsigned g_rel;                 // grid-barrier released epochs (monotonic)

// ---------------- helpers ----------------------------------------------------
#define L2E 1.4426950408889634f

__device__ __forceinline__ float lrelu_exp(float v)
{
    return exp2f(fmaxf(v, 0.2f * v) * L2E);
}
__device__ __forceinline__ float elu1(float v)
{
    return (v > 0.f) ? v : expm1f(v);
}
__device__ __forceinline__ uint32_t f2tf32(float v)
{
    uint32_t r; asm("cvt.rna.tf32.f32 %0, %1;" : "=r"(r) : "f"(v)); return r;
}
union U64 { ull u; float2 f; };

// ---------------- K1: x = h @ W  (tf32 tensor-core mma) -----------------------
__global__ void __launch_bounds__(256) k_gemm(const float* __restrict__ h,
                                              const float* __restrict__ W, int N)
{
    __shared__ uint32_t As[128][36];    // tf32 bits, row-major [m][k], pad 36
    __shared__ uint32_t Bs[32][72];     // tf32 bits, [k][n], pad 72

    const int tid  = threadIdx.x;
    const int m0   = blockIdx.x * 128;
    const int w    = tid >> 5;
    const int lane = tid & 31;
    const int lq   = lane >> 2;
    const int lr   = lane & 3;

    const int rowA = tid >> 3;
    const int kqA  = tid & 7;
    const int kkB  = tid >> 4;
    const int nqB  = tid & 15;

    float c[8][4];
#pragma unroll
    for (int nt = 0; nt < 8; nt++)
#pragma unroll
        for (int j = 0; j < 4; j++) c[nt][j] = 0.f;

    for (int k0 = 0; k0 < IND; k0 += 32) {
#pragma unroll
        for (int l = 0; l < 4; l++) {
            int row = rowA + 32 * l;
            int gm  = m0 + row;
            float4 v = make_float4(0.f, 0.f, 0.f, 0.f);
            if (gm < N) v = *(const float4*)(h + (size_t)gm * IND + k0 + kqA * 4);
            uint4 t;
            t.x = f2tf32(v.x); t.y = f2tf32(v.y); t.z = f2tf32(v.z); t.w = f2tf32(v.w);
            *(uint4*)&As[row][kqA * 4] = t;
        }
#pragma unroll
        for (int l = 0; l < 2; l++) {
            int kk = kkB + 16 * l;
            float4 v = *(const float4*)(W + (size_t)(k0 + kk) * OUTD + nqB * 4);
            uint4 t;
            t.x = f2tf32(v.x); t.y = f2tf32(v.y); t.z = f2tf32(v.z); t.w = f2tf32(v.w);
            *(uint4*)&Bs[kk][nqB * 4] = t;
        }
        __syncthreads();

#pragma unroll
        for (int kk = 0; kk < 32; kk += 8) {
            uint32_t a0 = As[w * 16 + lq][kk + lr];
            uint32_t a1 = As[w * 16 + lq + 8][kk + lr];
            uint32_t a2 = As[w * 16 + lq][kk + lr + 4];
            uint32_t a3 = As[w * 16 + lq + 8][kk + lr + 4];
#pragma unroll
            for (int nt = 0; nt < 8; nt++) {
                uint32_t b0 = Bs[kk + lr][nt * 8 + lq];
                uint32_t b1 = Bs[kk + lr + 4][nt * 8 + lq];
                asm("mma.sync.aligned.m16n8k8.row.col.f32.tf32.tf32.f32 "
                    "{%0,%1,%2,%3}, {%4,%5,%6,%7}, {%8,%9}, {%0,%1,%2,%3};"
                    : "+f"(c[nt][0]), "+f"(c[nt][1]), "+f"(c[nt][2]), "+f"(c[nt][3])
                    : "r"(a0), "r"(a1), "r"(a2), "r"(a3), "r"(b0), "r"(b1));
            }
        }
        __syncthreads();
    }

    const int r0 = m0 + w * 16 + lq;
#pragma unroll
    for (int nt = 0; nt < 8; nt++) {
        if (r0 < N)
            *(float2*)(g_x + (size_t)r0 * OUTD + nt * 8 + lr * 2) =
                make_float2(c[nt][0], c[nt][1]);
        if (r0 + 8 < N)
            *(float2*)(g_x + (size_t)(r0 + 8) * OUTD + nt * 8 + lr * 2) =
                make_float2(c[nt][2], c[nt][3]);
    }
}

// ---------------- K2: persistent CSR build (deg+scan+scatter, grid barrier) --
__global__ void __launch_bounds__(256) k_csr(const int* __restrict__ ei, int E, int N)
{
    __shared__ unsigned s_e0;
    __shared__ int s_scan[256];
    __shared__ int s_loc[256];

    const int tid = threadIdx.x;
    const int bid = blockIdx.x;
    const int stride = CSRB * 256;

    // cumulative epoch base (persists across graph replays; monotonic)
    if (tid == 0) s_e0 = atomicAdd(&g_rel, 0u);
    __syncthreads();
    unsigned kb = s_e0;

    auto gbar = [&]() {
        kb += 1;
        __syncthreads();
        if (tid == 0) {
            __threadfence();
            unsigned old = atomicAdd(&g_cnt, 1u);
            if (old == kb * CSRB - 1u) {
                atomicExch(&g_rel, kb);              // release this epoch
            } else {
                while ((int)(atomicAdd(&g_rel, 0u) - kb) < 0) __nanosleep(64);
            }
            __threadfence();
        }
        __syncthreads();
    };

    // ---- phase A: degree histogram ----
    {
        const int4* e4 = (const int4*)ei;
        int E4 = E >> 2;
        for (int i = bid * 256 + tid; i < E4; i += stride) {
            int4 v = e4[i];
            atomicAdd(&g_deg[v.x], 1);
            atomicAdd(&g_deg[v.y], 1);
            atomicAdd(&g_deg[v.z], 1);
            atomicAdd(&g_deg[v.w], 1);
        }
        for (int e = (E & ~3) + bid * 256 + tid; e < E; e += stride)
            atomicAdd(&g_deg[ei[e]], 1);
    }
    gbar();

    // ---- phase B: per-block local exclusive scan ----
    const int CHB = (N + CSRB - 1) / CSRB;           // elems per block (<=256)
    const int idx = bid * CHB + tid;
    {
        int v = (tid < CHB && idx < N) ? g_deg[idx] : 0;
        s_scan[tid] = v;
        __syncthreads();
#pragma unroll
        for (int o = 1; o < 256; o <<= 1) {
            int y = (tid >= o) ? s_scan[tid - o] : 0;
            __syncthreads();
            s_scan[tid] += y;
            __syncthreads();
        }
        s_loc[tid] = s_scan[tid] - v;
        if (tid == 255) g_blk[bid] = s_scan[255];
    }
    gbar();

    // ---- phase C: block 0 scans the 512 block totals ----
    if (bid == 0) {
        int a = g_blk[2 * tid];
        int c2 = g_blk[2 * tid + 1];
        int s = a + c2;
        s_scan[tid] = s;
        __syncthreads();
#pragma unroll
        for (int o = 1; o < 256; o <<= 1) {
            int y = (tid >= o) ? s_scan[tid - o] : 0;
            __syncthreads();
            s_scan[tid] += y;
            __syncthreads();
        }
        int ex = s_scan[tid] - s;
        g_blkoff[2 * tid]     = ex;
        g_blkoff[2 * tid + 1] = ex + a;
    }
    gbar();

    // ---- phase D: write offsets/cursors, re-zero deg ----
    {
        int base = g_blkoff[bid];
        if (tid < CHB && idx < N) {
            int o = base + s_loc[tid];
            g_off[idx] = o;
            g_cur[idx] = o;
            g_deg[idx] = 0;
        }
        if (bid == 0 && tid == 0) g_off[N] = E;
    }
    gbar();

    // ---- phase E: scatter (dst only), 4 edges/iter ----
    {
        int E4 = E >> 2;
        for (int i = bid * 256 + tid; i < E4; i += stride) {
            int4 s4 = *(const int4*)(ei + i * 4);
            int4 d4 = *(const int4*)(ei + E + i * 4);
            g_dst_s[atomicAdd(&g_cur[s4.x], 1)] = d4.x;
            g_dst_s[atomicAdd(&g_cur[s4.y], 1)] = d4.y;
            g_dst_s[atomicAdd(&g_cur[s4.z], 1)] = d4.z;
            g_dst_s[atomicAdd(&g_cur[s4.w], 1)] = d4.w;
        }
        for (int e = (E & ~3) + bid * 256 + tid; e < E; e += stride) {
            int s = ei[e];
            int d = ei[E + e];
            g_dst_s[atomicAdd(&g_cur[s], 1)] = d;
        }
    }
}

// ---------------- K3: el/er projections (warp per node) ----------------------
__global__ void k_elr(const float* __restrict__ Wl, const float* __restrict__ Wr, int N)
{
    int warp = (blockIdx.x * blockDim.x + threadIdx.x) >> 5;
    int lane = threadIdx.x & 31;
    if (warp >= N) return;

    const float* xr = g_x + (size_t)warp * OUTD;
    float x0 = xr[lane];
    float x1 = xr[lane + 32];

    float s[8];
#pragma unroll
    for (int hd = 0; hd < NH; hd++) {
        s[hd]     = x0 * __ldg(Wl + hd * OUTD + lane) + x1 * __ldg(Wl + hd * OUTD + lane + 32);
        s[4 + hd] = x0 * __ldg(Wr + hd * OUTD + lane) + x1 * __ldg(Wr + hd * OUTD + lane + 32);
    }
#pragma unroll
    for (int o = 16; o > 0; o >>= 1) {
#pragma unroll
        for (int j = 0; j < 8; j++) s[j] += __shfl_xor_sync(0xffffffffu, s[j], o);
    }
    if (lane == 0) {
        g_el[warp] = make_float4(s[0], s[1], s[2], s[3]);
        g_er[warp] = make_float4(s[4], s[5], s[6], s[7]);
    }
}

// ---------------- K4: per-node aggregation (round-7 proven version) ----------
__global__ void __launch_bounds__(128) k_agg(const float* __restrict__ b,
                                             float* __restrict__ out, int N)
{
    __shared__ int    s_off[2][4][32];
    __shared__ float4 s_e[2][4][32][2];

    const int w    = threadIdx.x >> 5;
    const int lane = threadIdx.x & 31;
    const int node = blockIdx.x * 4 + w;
    if (node >= N) return;

    const int s0 = g_off[node];
    const int s1 = g_off[node + 1];
    const float4 el = g_el[node];

    ull a0 = 0ull, a1 = 0ull, a2 = 0ull, a3 = 0ull;
    float e0 = 0.f, e1 = 0.f, e2 = 0.f, e3 = 0.f;

    const float* xl = g_x + lane * 2;

    auto stage = [&](int buf, int c, int n) {
        if (lane < n) {
            int d = g_dst_s[c + lane];
            float4 er = g_er[d];
            float ex = lrelu_exp(el.x + er.x);
            float ey = lrelu_exp(el.y + er.y);
            float ez = lrelu_exp(el.z + er.z);
            float ew = lrelu_exp(el.w + er.w);
            e0 += ex; e1 += ey; e2 += ez; e3 += ew;
            s_off[buf][w][lane]  = d * OUTD;
            s_e[buf][w][lane][0] = make_float4(ex, ex, ey, ey);
            s_e[buf][w][lane][1] = make_float4(ez, ez, ew, ew);
        }
    };

    auto consume32 = [&](int buf) {
        int oo0[4], oo1[4]; ull xx0[4], xx1[4];
#pragma unroll
        for (int q = 0; q < 4; q++) oo0[q] = s_off[buf][w][q];
#pragma unroll
        for (int q = 0; q < 4; q++) xx0[q] = *(const ull*)(xl + oo0[q]);
#pragma unroll
        for (int g = 0; g < 8; g++) {
            if (g < 7) {
#pragma unroll
                for (int q = 0; q < 4; q++) oo1[q] = s_off[buf][w][(g + 1) * 4 + q];
#pragma unroll
                for (int q = 0; q < 4; q++) xx1[q] = *(const ull*)(xl + oo1[q]);
            }
            ulonglong2 pa[4], pb[4];
#pragma unroll
            for (int q = 0; q < 4; q++) {
                pa[q] = *(const ulonglong2*)&s_e[buf][w][g * 4 + q][0];
                pb[q] = *(const ulonglong2*)&s_e[buf][w][g * 4 + q][1];
            }
#pragma unroll
            for (int q = 0; q < 4; q++) {
                asm("fma.rn.f32x2 %0, %1, %2, %0;" : "+l"(a0) : "l"(pa[q].x), "l"(xx0[q]));
                asm("fma.rn.f32x2 %0, %1, %2, %0;" : "+l"(a1) : "l"(pa[q].y), "l"(xx0[q]));
                asm("fma.rn.f32x2 %0, %1, %2, %0;" : "+l"(a2) : "l"(pb[q].x), "l"(xx0[q]));
                asm("fma.rn.f32x2 %0, %1, %2, %0;" : "+l"(a3) : "l"(pb[q].y), "l"(xx0[q]));
            }
#pragma unroll
            for (int q = 0; q < 4; q++) { xx0[q] = xx1[q]; oo0[q] = oo1[q]; }
        }
    };

    auto consumeTail = [&](int buf, int n) {
        for (int j = 0; j < n; j++) {
            int off = s_off[buf][w][j];
            ulonglong2 p0 = *(const ulonglong2*)&s_e[buf][w][j][0];
            ulonglong2 p1 = *(const ulonglong2*)&s_e[buf][w][j][1];
            ull xv = *(const ull*)(xl + off);
            asm("fma.rn.f32x2 %0, %1, %2, %0;" : "+l"(a0) : "l"(p0.x), "l"(xv));
            asm("fma.rn.f32x2 %0, %1, %2, %0;" : "+l"(a1) : "l"(p0.y), "l"(xv));
            asm("fma.rn.f32x2 %0, %1, %2, %0;" : "+l"(a2) : "l"(p1.x), "l"(xv));
            asm("fma.rn.f32x2 %0, %1, %2, %0;" : "+l"(a3) : "l"(p1.y), "l"(xv));
        }
    };

    int c = s0;
    int buf = 0;
    int n0 = s1 - c; if (n0 > 32) n0 = 32;
    stage(0, c, n0);
    __syncwarp();

    while (c + 32 < s1) {
        int cn = c + 32;
        int nn = s1 - cn; if (nn > 32) nn = 32;
        stage(buf ^ 1, cn, nn);
        consume32(buf);
        __syncwarp();
        buf ^= 1;
        c = cn;
    }
    {
        int n = s1 - c;
        if (n == 32) consume32(buf);
        else if (n > 0) consumeTail(buf, n);
    }

#pragma unroll
    for (int o = 16; o > 0; o >>= 1) {
        e0 += __shfl_xor_sync(0xffffffffu, e0, o);
        e1 += __shfl_xor_sync(0xffffffffu, e1, o);
        e2 += __shfl_xor_sync(0xffffffffu, e2, o);
        e3 += __shfl_xor_sync(0xffffffffu, e3, o);
    }

    float i0 = 1.f / fmaxf(e0, 1e-12f);
    float i1 = 1.f / fmaxf(e1, 1e-12f);
    float i2 = 1.f / fmaxf(e2, 1e-12f);
    float i3 = 1.f / fmaxf(e3, 1e-12f);

    float2 bb = *(const float2*)(b + lane * 2);

    U64 A0, A1, A2, A3;
    A0.u = a0; A1.u = a1; A2.u = a2; A3.u = a3;

    float* o = out + (size_t)node * (NH * OUTD) + lane * 2;
    float2 r;
    r.x = elu1(A0.f.x * i0 + bb.x); r.y = elu1(A0.f.y * i0 + bb.y);
    *(float2*)(o + 0 * OUTD) = r;
    r.x = elu1(A1.f.x * i1 + bb.x); r.y = elu1(A1.f.y * i1 + bb.y);
    *(float2*)(o + 1 * OUTD) = r;
    r.x = elu1(A2.f.x * i2 + bb.x); r.y = elu1(A2.f.y * i2 + bb.y);
    *(float2*)(o + 2 * OUTD) = r;
    r.x = elu1(A3.f.x * i3 + bb.x); r.y = elu1(A3.f.y * i3 + bb.y);
    *(float2*)(o + 3 * OUTD) = r;
}

// ---------------- launch: fork-join two-stream graph --------------------------
extern "C" void kernel_launch(void* const* d_in, const int* in_sizes, int n_in,
                              void* d_out, int out_size)
{
    const float* h  = (const float*)d_in[0];   // [N, 256]
    const float* W  = (const float*)d_in[1];   // [256, 64]
    const float* Wl = (const float*)d_in[2];   // [4, 64]
    const float* Wr = (const float*)d_in[3];   // [4, 64]
    const float* b  = (const float*)d_in[4];   // [64]
    const int*   ei = (const int*)d_in[5];     // [2, E]
    float* out = (float*)d_out;

    int N = in_sizes[0] / IND;
    int E = in_sizes[5] / 2;

    static cudaStream_t s1 = nullptr;
    static cudaEvent_t  evFork = nullptr, evJoin = nullptr;
    if (s1 == nullptr) {
        cudaStreamCreateWithFlags(&s1, cudaStreamNonBlocking);
        cudaEventCreateWithFlags(&evFork, cudaEventDisableTiming);
        cudaEventCreateWithFlags(&evJoin, cudaEventDisableTiming);
    }

    // fork: s1 builds the CSR in ONE persistent kernel
    cudaEventRecord(evFork, 0);
    cudaStreamWaitEvent(s1, evFork, 0);

    k_csr<<<CSRB, 256, 0, s1>>>(ei, E, N);
    cudaEventRecord(evJoin, s1);

    // main stream: gemm -> elr
    k_gemm<<<(N + 127) / 128, 256>>>(h, W, N);
    k_elr<<<(N + 7) / 8, 256>>>(Wl, Wr, N);

    // join: agg needs CSR (s1) + el/er (main)
    cudaStreamWaitEvent(0, evJoin, 0);
    k_agg<<<(N + 3) / 4, 128>>>(b, out, N);
}